// round 11
// baseline (speedup 1.0000x reference)
#include <cuda_runtime.h>
#include <math.h>

#define BB 2
#define DD 64
#define HH 96
#define WW 96
#define VOL (DD*HH*WW)          // 589824
#define NVOX (BB*VOL)           // 1179648
#define HWSZ (HH*WW)            // 9216
#define NPLANE (BB*DD)          // 128
#define HT 48                   // passBC h-tile (2 per plane)
#define WT3 32                  // pass3 w-tile
#define CLAMP 25.0f

#define NBLKBC (NPLANE*2*3)     // 768 passBC blocks
#define NBLK3 (BB*HH*(WW/WT3))  // 576 pass3 blocks

// Scratch (device globals: allocation-free per harness rules)
__device__ float g_x[NVOX];               // packed bp-bn after W+H transform (clamped 25)
__device__ volatile float g_pn[NBLK3];
__device__ volatile float g_pd[NBLK3];
__device__ unsigned g_count;              // zero-init; last block resets -> deterministic

// Windowed nearest-set-bit distance: 96-bit window {m0,m1,m2} covering
// [w0-32, w0+64); voxel at bit wl of m1. Only d<=5 matters (clamp).
__device__ __forceinline__ int win_dist(unsigned m0, unsigned m1, unsigned m2, int wl) {
    unsigned long long U = (unsigned long long)m1 | ((unsigned long long)m2 << 32);
    unsigned long long D = (unsigned long long)m0 | ((unsigned long long)m1 << 32);
    unsigned long long a = U >> wl;           // bit0 = self, upward
    unsigned long long b = D << (31 - wl);    // MSB = self, downward
    int up = a ? (__ffsll((long long)a) - 1) : 64;
    int dn = b ? __clzll((long long)b) : 64;
    return (up < dn) ? up : dn;
}

// Fused: windowed mask build + pass1 (clamped W bit-scan) + pass2 (k=1..4
// branch-free H stencil, register-staged). Block = (plane, h-half 48, w-tile 32).
__global__ __launch_bounds__(256) void k_passBC(const float* __restrict__ tgt) {
    __shared__ unsigned sm[HT + 8][3];    // rows h0-4..h0+51, segs wt-1..wt+1
    __shared__ float s1p[HT + 8][32];
    __shared__ float s1n[HT + 8][32];

    int blk = blockIdx.x;
    int wt = blk % 3;
    int ht = (blk / 3) & 1;
    int bd = blk / 6;
    int base = bd * HWSZ;
    int h0 = ht * HT;
    int tid = threadIdx.x;
    int lane = tid & 31;
    int warp = tid >> 5;                // 0..7

    // Ballot masks: 56 rows x 3 segs = 168 warp-tasks, 21 per warp.
    #pragma unroll
    for (int task = warp; task < (HT + 8) * 3; task += 8) {
        int r = task / 3;
        int s = task - r * 3;
        int hr = h0 - 4 + r;
        int sw = wt - 1 + s;
        unsigned m = 0;
        if (hr >= 0 && hr < HH && sw >= 0 && sw < 3) {
            float v = tgt[base + hr * WW + sw * 32 + lane];
            m = __ballot_sync(0xFFFFFFFFu, v > 0.5f);
        }
        if (lane == 0) sm[r][s] = m;
    }
    __syncthreads();

    // pass1: clamped W-distance via windowed bit scan; out-of-plane rows -> CLAMP.
    unsigned val0 = (wt > 0) ? 0xFFFFFFFFu : 0u;
    unsigned val2 = (wt < 2) ? 0xFFFFFFFFu : 0u;
    #pragma unroll
    for (int r = warp; r < HT + 8; r += 8) {
        int hr = h0 - 4 + r;
        float vp, vn;
        if (hr < 0 || hr >= HH) {
            vp = CLAMP; vn = CLAMP;
        } else {
            unsigned m0 = sm[r][0], m1 = sm[r][1], m2 = sm[r][2];
            int dn = win_dist(m0, m1, m2, lane);                       // nearest 1
            int dp = win_dist(val0 & ~m0, ~m1, val2 & ~m2, lane);      // nearest 0
            vp = (dp >= 5) ? CLAMP : (float)(dp * dp);
            vn = (dn >= 5) ? CLAMP : (float)(dn * dn);
        }
        s1p[r][lane] = vp;
        s1n[r][lane] = vn;
    }
    __syncthreads();

    // pass2: each warp takes 6 consecutive rows; stage the 14-row window in
    // registers (28 LDS per 6 voxels), fixed k=1..4 stencil (exact under clamp).
    {
        int r0 = warp * 6;              // smem rows r0 .. r0+13 cover voxels r0+4..r0+9
        float ap[14], an[14];
        #pragma unroll
        for (int j = 0; j < 14; ++j) {
            ap[j] = s1p[r0 + j][lane];
            an[j] = s1n[r0 + j][lane];
        }
        #pragma unroll
        for (int v = 0; v < 6; ++v) {
            float bp = ap[v + 4];
            float bn = an[v + 4];
            #pragma unroll
            for (int k = 1; k <= 4; ++k) {
                float k2 = (float)(k * k);
                bp = fminf(bp, ap[v + 4 - k] + k2);
                bp = fminf(bp, ap[v + 4 + k] + k2);
                bn = fminf(bn, an[v + 4 - k] + k2);
                bn = fminf(bn, an[v + 4 + k] + k2);
            }
            // Exactly one of bp,bn is 0 -> pack as signed value.
            int h = h0 + warp * 6 + v;
            g_x[base + h * WW + wt * 32 + lane] = bp - bn;
        }
    }
}

// Pass3: k=1..4 D-stencil, 8 voxels/thread with register-staged 16-row window,
// fused loss epilogue (two group-4 logs) + grid-final reduction.
__global__ __launch_bounds__(256) void k_pass3(const float* __restrict__ pred,
                                               float* __restrict__ out) {
    __shared__ float sfp[DD + 8][33];   // stride 33: lane=w conflict-free
    __shared__ float sfn[DD + 8][33];
    __shared__ float rnm[8], rdm[8];
    __shared__ int s_last;

    int wt = blockIdx.x % (WW / WT3);       // 0..2
    int bh = blockIdx.x / (WW / WT3);
    int b = bh / HH;
    int h = bh % HH;
    int base = b * VOL + h * WW + wt * WT3;
    int tid = threadIdx.x;
    int w = tid & 31;
    int c0 = tid >> 5;                      // 0..7
    int i0 = c0 * 8;                        // 8 consecutive i per thread

    // Issue pred LDGs first (latency hidden behind smem fill + stencil).
    float pv[8];
    #pragma unroll
    for (int j = 0; j < 8; ++j) pv[j] = pred[base + (i0 + j) * HWSZ + w];

    // Pad rows [0..3] and [DD+4..DD+7].
    {
        int r = tid >> 5;                   // 0..7
        int row = (r < 4) ? r : (DD + r);
        sfp[row][w] = CLAMP;
        sfn[row][w] = CLAMP;
    }
    // Load + decode packed values (coalesced 128B per warp).
    #pragma unroll
    for (int r = tid; r < DD * 32; r += 256) {
        int d = r >> 5, ww_ = r & 31;
        float x = g_x[base + d * HWSZ + ww_];
        sfp[4 + d][ww_] = fmaxf(x, 0.0f);
        sfn[4 + d][ww_] = fmaxf(-x, 0.0f);
    }
    __syncthreads();

    // Stage the 16 needed rows into registers (shared across 8 voxels).
    float rp[16], rn_[16];
    #pragma unroll
    for (int j = 0; j < 16; ++j) {
        rp[j]  = sfp[i0 + j][w];    // smem rows i0 .. i0+15
        rn_[j] = sfn[i0 + j][w];
    }

    float mArr[8], pcArr[8];
    #pragma unroll
    for (int j = 0; j < 8; ++j) {
        float bp = rp[j + 4];
        float bn = rn_[j + 4];
        #pragma unroll
        for (int k = 1; k <= 4; ++k) {
            float k2 = (float)(k * k);
            bp = fminf(bp, rp[j + 4 - k] + k2);
            bp = fminf(bp, rp[j + 4 + k] + k2);
            bn = fminf(bn, rn_[j + 4 - k] + k2);
            bn = fminf(bn, rn_[j + 4 + k] + k2);
        }
        mArr[j] = fmaxf(bp, bn);                    // exactly one is 0
        pcArr[j] = (bp > 0.0f) ? pv[j] : (1.0f - pv[j]);   // t==1 <=> bp>0
    }

    float accn = 0.0f, accd = 0.0f;
    #pragma unroll
    for (int g = 0; g < 2; ++g) {
        bool fast = true;
        float prod = 1.0f;
        #pragma unroll
        for (int j = 4 * g; j < 4 * g + 4; ++j) {
            if (mArr[j] > 9.0f) fast = false;
            prod *= pcArr[j];
        }
        if (fast && prod > 1e-30f) {
            accn += -__logf(prod);     // all w==1: sum(-log pc) == -log(prod)
            accd += 4.0f;
        } else {
            #pragma unroll
            for (int j = 4 * g; j < 4 * g + 4; ++j) {
                float m = mArr[j];
                float wgt;
                if (m <= 9.0f)       wgt = 1.0f;
                else if (m >= 25.0f) wgt = 0.0f;
                else                 wgt = 1.0f - (sqrtf(m) - 3.0f) * 0.5f;
                float bce = -fmaxf(__logf(pcArr[j]), -100.0f);
                accn += bce * wgt;
                accd += wgt;
            }
        }
    }

    #pragma unroll
    for (int off = 16; off > 0; off >>= 1) {
        accn += __shfl_down_sync(0xFFFFFFFFu, accn, off);
        accd += __shfl_down_sync(0xFFFFFFFFu, accd, off);
    }
    int warp = tid >> 5, lane = tid & 31;
    if (lane == 0) { rnm[warp] = accn; rdm[warp] = accd; }
    __syncthreads();
    if (tid == 0) {
        float sn = 0.0f, sd = 0.0f;
        #pragma unroll
        for (int j = 0; j < 8; ++j) { sn += rnm[j]; sd += rdm[j]; }
        g_pn[blockIdx.x] = sn;
        g_pd[blockIdx.x] = sd;
        __threadfence();
        unsigned old = atomicAdd(&g_count, 1u);
        s_last = (old == NBLK3 - 1) ? 1 : 0;
    }
    __syncthreads();

    // Last block: reduce all 576 partials -> scalar, reset counter.
    if (s_last) {
        __shared__ double wn[8], wd[8];
        const int PER_B = NBLK3 / BB;     // 288
        int rb = tid >> 7;                // 0..1 (batch)
        int j0 = tid & 127;
        double an = 0.0, ad = 0.0;
        #pragma unroll
        for (int j = j0; j < PER_B; j += 128) {
            an += (double)g_pn[rb * PER_B + j];
            ad += (double)g_pd[rb * PER_B + j];
        }
        #pragma unroll
        for (int off = 16; off > 0; off >>= 1) {
            an += __shfl_down_sync(0xFFFFFFFFu, an, off);
            ad += __shfl_down_sync(0xFFFFFFFFu, ad, off);
        }
        if (lane == 0) { wn[warp] = an; wd[warp] = ad; }
        __syncthreads();
        if (tid == 0) {
            double n0 = 0.0, dd0 = 0.0, n1 = 0.0, dd1 = 0.0;
            #pragma unroll
            for (int j = 0; j < 4; ++j) { n0 += wn[j]; dd0 += wd[j]; }
            #pragma unroll
            for (int j = 4; j < 8; ++j) { n1 += wn[j]; dd1 += wd[j]; }
            double acc = n0 / (dd0 + 1e-5) + n1 / (dd1 + 1e-5);
            out[0] = (float)(acc / (double)BB);
            g_count = 0;   // reset for next graph replay
        }
    }
}

extern "C" void kernel_launch(void* const* d_in, const int* in_sizes, int n_in,
                              void* d_out, int out_size) {
    const float* pred = (const float*)d_in[0];
    const float* tgt  = (const float*)d_in[1];
    (void)in_sizes; (void)n_in; (void)out_size;

    k_passBC<<<NBLKBC, 256>>>(tgt);                 // 768 blocks
    k_pass3<<<NBLK3, 256>>>(pred, (float*)d_out);   // 576 blocks
}

// round 12
// speedup vs baseline: 1.2886x; 1.2886x over previous
#include <cuda_runtime.h>
#include <math.h>

#define BB 2
#define DD 64
#define HH 96
#define WW 96
#define VOL (DD*HH*WW)          // 589824
#define NVOX (BB*VOL)           // 1179648
#define HWSZ (HH*WW)            // 9216
#define NPLANE (BB*DD)          // 128
#define WT 32                   // passBC w-tile
#define HT 24                   // passBC h-tile (4 per plane)
#define WT3 16                  // pass3 w-tile
#define CLAMP 25.0f

#define NBLKBC (NPLANE*3*4)     // 1536 passBC blocks
#define NBLK3 (BB*HH*(WW/WT3))  // 1152 pass3 blocks

// Scratch (device globals: allocation-free per harness rules)
__device__ float g_x[NVOX];               // packed bp-bn after W+H transform (clamped 25)
__device__ volatile float g_pn[NBLK3];
__device__ volatile float g_pd[NBLK3];
__device__ unsigned g_count;              // zero-init; last block resets -> deterministic

// Windowed nearest-set-bit distance: 96-bit local window {m0,m1,m2} covering
// [w0-32, w0+64); voxel at bit wl of m1. Clamp guarantees only d<=5 matters.
__device__ __forceinline__ int win_dist(unsigned m0, unsigned m1, unsigned m2, int wl) {
    unsigned long long U = (unsigned long long)m1 | ((unsigned long long)m2 << 32);
    unsigned long long D = (unsigned long long)m0 | ((unsigned long long)m1 << 32);
    unsigned long long a = U >> wl;           // bit0 = self, upward
    unsigned long long b = D << (31 - wl);    // MSB = self, downward
    int up = a ? (__ffsll((long long)a) - 1) : 64;
    int dn = b ? __clzll((long long)b) : 64;
    return (up < dn) ? up : dn;
}

// Fused: windowed mask build + pass1 (clamped W bit-scan) + pass2 (k=1..4
// branch-free H stencil, packed smem). Block = (plane, h-tile 24, w-tile 32).
__global__ __launch_bounds__(256) void k_passBC(const float* __restrict__ tgt) {
    __shared__ unsigned sm[32][3];      // rows h0-4..h0+27, segs wt-1..wt+1
    __shared__ float s1x[32][WT];       // packed vp - vn

    int blk = blockIdx.x;
    int wt = blk % 3;
    int ht = (blk / 3) & 3;
    int bd = blk / 12;
    int base = bd * HWSZ;
    int h0 = ht * HT;
    int tid = threadIdx.x;
    int lane = tid & 31;
    int warp = tid >> 5;                // 0..7

    // Ballot masks: 96 warp-tasks (32 rows x 3 segs), 12 per warp.
    #pragma unroll
    for (int task = warp; task < 96; task += 8) {
        int r = task / 3;
        int s = task - r * 3;
        int hr = h0 - 4 + r;
        int sw = wt - 1 + s;
        unsigned m = 0;
        if (hr >= 0 && hr < HH && sw >= 0 && sw < 3) {
            float v = tgt[base + hr * WW + sw * 32 + lane];
            m = __ballot_sync(0xFFFFFFFFu, v > 0.5f);
        }
        if (lane == 0) sm[r][s] = m;
    }
    __syncthreads();

    // pass1: clamped W-distance via windowed bit scan; rows outside plane get
    // {CLAMP, CLAMP} -> packed 0? NO: pack vp - vn = 0 would decode as (0,0).
    // Use a neutral sentinel: both CLAMP decodes must yield CLAMP,CLAMP -> store
    // them via a separate marker. Instead: out-of-plane rows pack as 0 is wrong;
    // encode vp-vn only valid when one side is 0. For pad rows use +CLAMP with
    // vn side also clamped by construction of the stencil: a pad row contributes
    // fmax(x,0)+k2 to bp and fmax(-x,0)+k2 to bn. We need both >= CLAMP.
    // Trick: store pads as NaN-free two-sided by using x = 0 and adding k2>=1?
    // Not exact. Solution: pad rows store x = CLAMP for bp side and the bn side
    // decode fmax(-CLAMP,0)=0 +k2 which could wrongly lower bn. Therefore pads
    // must NOT exist: restrict stencil reads to valid plane rows by clamping the
    // index (reads of row -k map to row 0 region handled below). We keep a
    // 4-row halo INSIDE the plane (h0-4..h0+27 all within [?,?]) and for plane
    // borders (hr<0 or hr>=HH) we fall back to two separate smem arrays just
    // for those rows -- simpler: store halo validity via second tiny array.
    __shared__ float s1pad[32][2];      // unused lanes; per-row {padp, padn} flags
    #pragma unroll
    for (int r = warp; r < 32; r += 8) {
        int hr = h0 - 4 + r;
        float x;
        if (hr < 0 || hr >= HH) {
            x = 0.0f;                   // decoded as (0,0) but masked via s1pad
            if (lane == 0) { s1pad[r][0] = CLAMP; s1pad[r][1] = CLAMP; }
        } else {
            unsigned m0 = sm[r][0], m1 = sm[r][1], m2 = sm[r][2];
            unsigned val0 = (wt > 0) ? 0xFFFFFFFFu : 0u;
            unsigned val2 = (wt < 2) ? 0xFFFFFFFFu : 0u;
            int dn = win_dist(m0, m1, m2, lane);                       // nearest 1
            int dp = win_dist(val0 & ~m0, ~m1, val2 & ~m2, lane);      // nearest 0
            float vp = (dp >= 5) ? CLAMP : (float)(dp * dp);
            float vn = (dn >= 5) ? CLAMP : (float)(dn * dn);
            x = vp - vn;                // exactly one of vp,vn is 0
            if (lane == 0) { s1pad[r][0] = 0.0f; s1pad[r][1] = 0.0f; }
        }
        s1x[r][lane] = x;
    }
    __syncthreads();

    // pass2 along H: fixed k=1..4 stencil on packed values; per-row pad offset
    // (0 for valid rows, CLAMP for pad rows -> contribution >= CLAMP, exact).
    #pragma unroll
    for (int r4 = warp; r4 < HT; r4 += 8) {
        int r = r4 + 4;
        float xc = s1x[r][lane];
        float bp = fmaxf(xc, 0.0f);
        float bn = fmaxf(-xc, 0.0f);
        #pragma unroll
        for (int k = 1; k <= 4; ++k) {
            float k2 = (float)(k * k);
            float xm = s1x[r - k][lane];
            float xp_ = s1x[r + k][lane];
            float pm0 = s1pad[r - k][0], pm1 = s1pad[r - k][1];
            float pp0 = s1pad[r + k][0], pp1 = s1pad[r + k][1];
            bp = fminf(bp, fmaxf(xm, 0.0f) + pm0 + k2);
            bp = fminf(bp, fmaxf(xp_, 0.0f) + pp0 + k2);
            bn = fminf(bn, fmaxf(-xm, 0.0f) + pm1 + k2);
            bn = fminf(bn, fmaxf(-xp_, 0.0f) + pp1 + k2);
        }
        g_x[base + (h0 + r4) * WW + wt * WT + lane] = bp - bn;
    }
}

// Pass3: k=1..4 D-stencil on packed smem (register-staged x[12]), fused loss
// epilogue (group-4 log) + grid-final reduction.
__global__ __launch_bounds__(256) void k_pass3(const float* __restrict__ pred,
                                               float* __restrict__ out) {
    __shared__ float sfx[DD + 8][17];   // packed; stride 17: no bank conflicts
    __shared__ float rnm[8], rdm[8];
    __shared__ int s_last;

    int wt = blockIdx.x % (WW / WT3);       // 0..5
    int bh = blockIdx.x / (WW / WT3);
    int b = bh / HH;
    int h = bh % HH;
    int base = b * VOL + h * WW + wt * WT3;
    int tid = threadIdx.x;
    int w = tid & 15;
    int c0 = tid >> 4;                      // 0..15
    int i0 = c0 * 4;                        // 4 consecutive i per thread

    // Issue pred LDGs first (latency hidden behind smem fill + stencil).
    float pv[4];
    #pragma unroll
    for (int j = 0; j < 4; ++j) pv[j] = pred[base + (i0 + j) * HWSZ + w];

    // Pad rows [0..3] and [DD+4..DD+7]: packed CLAMP works for the bp side
    // (decodes to (CLAMP,0)) but NOT bn. D-pads need both sides >= CLAMP.
    // Use the sign trick per pad row: alternate is impossible with one float.
    // Instead store +CLAMP in pads and handle the bn side by symmetry: the
    // stencil uses fmax(-x,0); for pad x=+CLAMP that's 0+k2 -- WRONG.
    // Fix: D-pad rows are known at compile position; handle boundary via
    // index clamping instead of pads: for voxel i, neighbor i±k outside [0,DD)
    // maps to row i (self, adds k2 >= 1; can only lower toward self+k2 which
    // is >= min already? self+k2 >= bp_current? bp starts at self, so
    // fmin(bp, self+k2) = bp. EXACT no-op). So clamp indices to [0, DD-1]...
    // careful: clamped to 0 or DD-1 (not self) would read a DIFFERENT row and
    // could wrongly lower. Must clamp such that contribution is a no-op:
    // map out-of-range to the center row i itself.
    #pragma unroll
    for (int r = tid; r < DD * WT3; r += 256) {
        int d = r >> 4, ww_ = r & 15;
        sfx[d][ww_] = g_x[base + d * HWSZ + ww_];
    }
    __syncthreads();

    // Stage 12-row window into registers, mapping out-of-range rows to the
    // center row (fmin no-op, exact).
    float mArr[4], pcArr[4];
    #pragma unroll
    for (int j = 0; j < 4; ++j) {
        int i = i0 + j;
        float xc = sfx[i][w];
        float bp = fmaxf(xc, 0.0f);
        float bn = fmaxf(-xc, 0.0f);
        #pragma unroll
        for (int k = 1; k <= 4; ++k) {
            float k2 = (float)(k * k);
            int lo = i - k, hi = i + k;
            float xl = (lo >= 0) ? sfx[lo][w] : xc;   // self -> no-op
            float xh = (hi < DD) ? sfx[hi][w] : xc;
            bp = fminf(bp, fmaxf(xl, 0.0f) + k2);
            bp = fminf(bp, fmaxf(xh, 0.0f) + k2);
            bn = fminf(bn, fmaxf(-xl, 0.0f) + k2);
            bn = fminf(bn, fmaxf(-xh, 0.0f) + k2);
        }
        mArr[j] = fmaxf(bp, bn);                    // exactly one is 0
        pcArr[j] = (bp > 0.0f) ? pv[j] : (1.0f - pv[j]);   // t==1 <=> bp>0
    }

    float accn, accd;
    bool fast = true;
    float prod = 1.0f;
    #pragma unroll
    for (int j = 0; j < 4; ++j) {
        if (mArr[j] > 9.0f) fast = false;
        prod *= pcArr[j];
    }
    if (fast && prod > 1e-30f) {
        accn = -__logf(prod);      // all w==1: sum(-log pc) == -log(prod)
        accd = 4.0f;
    } else {
        accn = 0.0f; accd = 0.0f;
        #pragma unroll
        for (int j = 0; j < 4; ++j) {
            float m = mArr[j];
            float wgt;
            if (m <= 9.0f)       wgt = 1.0f;
            else if (m >= 25.0f) wgt = 0.0f;
            else                 wgt = 1.0f - (sqrtf(m) - 3.0f) * 0.5f;
            float bce = -fmaxf(__logf(pcArr[j]), -100.0f);
            accn += bce * wgt;
            accd += wgt;
        }
    }

    #pragma unroll
    for (int off = 16; off > 0; off >>= 1) {
        accn += __shfl_down_sync(0xFFFFFFFFu, accn, off);
        accd += __shfl_down_sync(0xFFFFFFFFu, accd, off);
    }
    int warp = tid >> 5, lane = tid & 31;
    if (lane == 0) { rnm[warp] = accn; rdm[warp] = accd; }
    __syncthreads();
    if (tid == 0) {
        float sn = 0.0f, sd = 0.0f;
        #pragma unroll
        for (int j = 0; j < 8; ++j) { sn += rnm[j]; sd += rdm[j]; }
        g_pn[blockIdx.x] = sn;
        g_pd[blockIdx.x] = sd;
        __threadfence();
        unsigned old = atomicAdd(&g_count, 1u);
        s_last = (old == NBLK3 - 1) ? 1 : 0;
    }
    __syncthreads();

    // Last block: reduce all 1152 partials -> scalar, reset counter.
    if (s_last) {
        __shared__ double wn[8], wd[8];
        const int PER_B = NBLK3 / BB;     // 576
        int rb = tid >> 7;                // 0..1 (batch)
        int j0 = tid & 127;
        double an = 0.0, ad = 0.0;
        #pragma unroll
        for (int j = j0; j < PER_B; j += 128) {
            an += (double)g_pn[rb * PER_B + j];
            ad += (double)g_pd[rb * PER_B + j];
        }
        #pragma unroll
        for (int off = 16; off > 0; off >>= 1) {
            an += __shfl_down_sync(0xFFFFFFFFu, an, off);
            ad += __shfl_down_sync(0xFFFFFFFFu, ad, off);
        }
        if (lane == 0) { wn[warp] = an; wd[warp] = ad; }
        __syncthreads();
        if (tid == 0) {
            double n0 = 0.0, dd0 = 0.0, n1 = 0.0, dd1 = 0.0;
            #pragma unroll
            for (int j = 0; j < 4; ++j) { n0 += wn[j]; dd0 += wd[j]; }
            #pragma unroll
            for (int j = 4; j < 8; ++j) { n1 += wn[j]; dd1 += wd[j]; }
            double acc = n0 / (dd0 + 1e-5) + n1 / (dd1 + 1e-5);
            out[0] = (float)(acc / (double)BB);
            g_count = 0;   // reset for next graph replay
        }
    }
}

extern "C" void kernel_launch(void* const* d_in, const int* in_sizes, int n_in,
                              void* d_out, int out_size) {
    const float* pred = (const float*)d_in[0];
    const float* tgt  = (const float*)d_in[1];
    (void)in_sizes; (void)n_in; (void)out_size;

    k_passBC<<<NBLKBC, 256>>>(tgt);                 // 1536 blocks
    k_pass3<<<NBLK3, 256>>>(pred, (float*)d_out);   // 1152 blocks
}

// round 13
// speedup vs baseline: 1.5341x; 1.1905x over previous
#include <cuda_runtime.h>
#include <math.h>

#define BB 2
#define DD 64
#define HH 96
#define WW 96
#define VOL (DD*HH*WW)          // 589824
#define NVOX (BB*VOL)           // 1179648
#define HWSZ (HH*WW)            // 9216
#define NPLANE (BB*DD)          // 128
#define NROWS (NPLANE*HH)       // 12288
#define WT 32                   // passBC w-tile
#define HT 24                   // passBC h-tile (4 per plane)
#define WT3 16                  // pass3 w-tile
#define CLAMP 25.0f

#define NBLKBC (NPLANE*3*4)     // 1536 passBC blocks
#define NBLK3 (BB*HH*(WW/WT3))  // 1152 pass3 blocks

// Scratch (device globals: allocation-free per harness rules)
__device__ unsigned g_mask[NROWS][3];     // 96-bit row masks
__device__ float g_x[NVOX];               // packed bp-bn after W+H transform (clamped 25)
__device__ volatile float g_pn[NBLK3];
__device__ volatile float g_pd[NBLK3];
__device__ unsigned g_count;              // zero-init; last block resets -> deterministic

// Windowed nearest-set-bit distance: 96-bit local window {m0,m1,m2} covering
// [w0-32, w0+64); voxel at bit wl of m1. Clamp usage guarantees d<=5 matters.
__device__ __forceinline__ int win_dist(unsigned m0, unsigned m1, unsigned m2, int wl) {
    unsigned long long U = (unsigned long long)m1 | ((unsigned long long)m2 << 32);
    unsigned long long D = (unsigned long long)m0 | ((unsigned long long)m1 << 32);
    unsigned long long a = U >> wl;           // bit0 = self, upward
    unsigned long long b = D << (31 - wl);    // MSB = self, downward
    int up = a ? (__ffsll((long long)a) - 1) : 64;
    int dn = b ? __clzll((long long)b) : 64;
    return (up < dn) ? up : dn;
}

// Build row masks once: one warp per row, 3 coalesced LDGs (MLP=3) + 3 ballots.
// Reads tgt exactly once (4.7 MB total).
__global__ __launch_bounds__(256) void k_mask(const float* __restrict__ tgt) {
    int gw = (blockIdx.x * 256 + threadIdx.x) >> 5;   // 0..NROWS-1
    int lane = threadIdx.x & 31;
    const float* row = tgt + gw * WW;
    float v0 = row[lane];
    float v1 = row[lane + 32];
    float v2 = row[lane + 64];
    unsigned m0 = __ballot_sync(0xFFFFFFFFu, v0 > 0.5f);
    unsigned m1 = __ballot_sync(0xFFFFFFFFu, v1 > 0.5f);
    unsigned m2 = __ballot_sync(0xFFFFFFFFu, v2 > 0.5f);
    if (lane == 0) {
        g_mask[gw][0] = m0;
        g_mask[gw][1] = m1;
        g_mask[gw][2] = m2;
    }
}

// Fused pass1 (clamped W bit-scan from masks) + pass2 (k=1..4 branch-free
// H stencil in smem). Block = (plane, h-tile 24, w-tile 32). Round-10 shape.
__global__ __launch_bounds__(256) void k_passBC() {
    __shared__ unsigned sm[32][3];      // rows h0-4..h0+27, segs wt-1..wt+1
    __shared__ float s1p[32][WT];
    __shared__ float s1n[32][WT];

    int blk = blockIdx.x;
    int wt = blk % 3;
    int ht = (blk / 3) & 3;
    int bd = blk / 12;
    int base = bd * HWSZ;
    int h0 = ht * HT;
    int tid = threadIdx.x;
    int lane = tid & 31;
    int warp = tid >> 5;                // 0..7

    // Load the 96 mask words (384 B) instead of re-ballots on tgt.
    if (tid < 96) {
        int r = tid / 3, s = tid - (tid / 3) * 3;
        int hr = h0 - 4 + r;
        int sw = wt - 1 + s;
        unsigned m = 0;
        if (hr >= 0 && hr < HH && sw >= 0 && sw < 3)
            m = g_mask[bd * HH + hr][sw];
        sm[r][s] = m;
    }
    __syncthreads();

    // pass1: clamped W-distance via windowed bit scan; out-of-plane rows -> CLAMP.
    unsigned val0 = (wt > 0) ? 0xFFFFFFFFu : 0u;
    unsigned val2 = (wt < 2) ? 0xFFFFFFFFu : 0u;
    #pragma unroll
    for (int r = warp; r < 32; r += 8) {
        int hr = h0 - 4 + r;
        float vp, vn;
        if (hr < 0 || hr >= HH) {
            vp = CLAMP; vn = CLAMP;
        } else {
            unsigned m0 = sm[r][0], m1 = sm[r][1], m2 = sm[r][2];
            int dn = win_dist(m0, m1, m2, lane);                       // nearest 1
            int dp = win_dist(val0 & ~m0, ~m1, val2 & ~m2, lane);      // nearest 0
            vp = (dp >= 5) ? CLAMP : (float)(dp * dp);
            vn = (dn >= 5) ? CLAMP : (float)(dn * dn);
        }
        s1p[r][lane] = vp;
        s1n[r][lane] = vn;
    }
    __syncthreads();

    // pass2 along H: fixed k=1..4 stencil (k=5 -> 25 >= clamp), rows 4..27.
    #pragma unroll
    for (int r4 = warp; r4 < HT; r4 += 8) {
        int r = r4 + 4;
        float bp = s1p[r][lane];
        float bn = s1n[r][lane];
        #pragma unroll
        for (int k = 1; k <= 4; ++k) {
            float k2 = (float)(k * k);
            bp = fminf(bp, s1p[r - k][lane] + k2);
            bp = fminf(bp, s1p[r + k][lane] + k2);
            bn = fminf(bn, s1n[r - k][lane] + k2);
            bn = fminf(bn, s1n[r + k][lane] + k2);
        }
        // Exactly one of bp,bn is 0 -> pack as signed value.
        g_x[base + (h0 + r4) * WW + wt * WT + lane] = bp - bn;
    }
}

// Pass3: k=1..4 D-stencil with 4-consecutive-i register reuse, fused loss
// epilogue (group-4 log) + grid-final reduction. Exact round-10 shape.
__global__ __launch_bounds__(256) void k_pass3(const float* __restrict__ pred,
                                               float* __restrict__ out) {
    __shared__ float sfp[DD + 8][17];   // stride 17: no bank conflicts
    __shared__ float sfn[DD + 8][17];
    __shared__ float rnm[8], rdm[8];
    __shared__ int s_last;

    int wt = blockIdx.x % (WW / WT3);       // 0..5
    int bh = blockIdx.x / (WW / WT3);
    int b = bh / HH;
    int h = bh % HH;
    int base = b * VOL + h * WW + wt * WT3;
    int tid = threadIdx.x;
    int w = tid & 15;
    int c0 = tid >> 4;                      // 0..15
    int i0 = c0 * 4;                        // 4 consecutive i per thread

    // Issue pred LDGs first (latency hidden behind smem fill + stencil).
    float pv[4];
    #pragma unroll
    for (int j = 0; j < 4; ++j) pv[j] = pred[base + (i0 + j) * HWSZ + w];

    // Pad rows [0..3] and [DD+4..DD+7].
    if (tid < 128) {
        int r = tid >> 4;
        int ww_ = tid & 15;
        int row = (r < 4) ? r : (DD + r);
        sfp[row][ww_] = CLAMP;
        sfn[row][ww_] = CLAMP;
    }
    // Load + decode packed values (coalesced 64B per 16 lanes).
    #pragma unroll
    for (int r = tid; r < DD * WT3; r += 256) {
        int d = r >> 4, ww_ = r & 15;
        float x = g_x[base + d * HWSZ + ww_];
        sfp[4 + d][ww_] = fmaxf(x, 0.0f);
        sfn[4 + d][ww_] = fmaxf(-x, 0.0f);
    }
    __syncthreads();

    // Pull the 12 needed rows into registers (shared across 4 voxels).
    float rp[12], rn_[12];
    #pragma unroll
    for (int j = 0; j < 12; ++j) {
        rp[j]  = sfp[i0 + j][w];    // covers padded rows i0 .. i0+11
        rn_[j] = sfn[i0 + j][w];
    }

    float mArr[4], pcArr[4];
    #pragma unroll
    for (int j = 0; j < 4; ++j) {
        float bp = rp[j + 4];
        float bn = rn_[j + 4];
        #pragma unroll
        for (int k = 1; k <= 4; ++k) {
            float k2 = (float)(k * k);
            bp = fminf(bp, rp[j + 4 - k] + k2);
            bp = fminf(bp, rp[j + 4 + k] + k2);
            bn = fminf(bn, rn_[j + 4 - k] + k2);
            bn = fminf(bn, rn_[j + 4 + k] + k2);
        }
        mArr[j] = fmaxf(bp, bn);                    // exactly one is 0
        pcArr[j] = (bp > 0.0f) ? pv[j] : (1.0f - pv[j]);   // t==1 <=> bp>0
    }

    float accn, accd;
    bool fast = true;
    float prod = 1.0f;
    #pragma unroll
    for (int j = 0; j < 4; ++j) {
        if (mArr[j] > 9.0f) fast = false;
        prod *= pcArr[j];
    }
    if (fast && prod > 1e-30f) {
        accn = -__logf(prod);      // all w==1: sum(-log pc) == -log(prod)
        accd = 4.0f;
    } else {
        accn = 0.0f; accd = 0.0f;
        #pragma unroll
        for (int j = 0; j < 4; ++j) {
            float m = mArr[j];
            float wgt;
            if (m <= 9.0f)       wgt = 1.0f;
            else if (m >= 25.0f) wgt = 0.0f;
            else                 wgt = 1.0f - (sqrtf(m) - 3.0f) * 0.5f;
            float bce = -fmaxf(__logf(pcArr[j]), -100.0f);
            accn += bce * wgt;
            accd += wgt;
        }
    }

    #pragma unroll
    for (int off = 16; off > 0; off >>= 1) {
        accn += __shfl_down_sync(0xFFFFFFFFu, accn, off);
        accd += __shfl_down_sync(0xFFFFFFFFu, accd, off);
    }
    int warp = tid >> 5, lane = tid & 31;
    if (lane == 0) { rnm[warp] = accn; rdm[warp] = accd; }
    __syncthreads();
    if (tid == 0) {
        float sn = 0.0f, sd = 0.0f;
        #pragma unroll
        for (int j = 0; j < 8; ++j) { sn += rnm[j]; sd += rdm[j]; }
        g_pn[blockIdx.x] = sn;
        g_pd[blockIdx.x] = sd;
        __threadfence();
        unsigned old = atomicAdd(&g_count, 1u);
        s_last = (old == NBLK3 - 1) ? 1 : 0;
    }
    __syncthreads();

    // Last block: reduce all 1152 partials -> scalar, reset counter.
    if (s_last) {
        __shared__ double wn[8], wd[8];
        const int PER_B = NBLK3 / BB;     // 576
        int rb = tid >> 7;                // 0..1 (batch)
        int j0 = tid & 127;
        double an = 0.0, ad = 0.0;
        #pragma unroll
        for (int j = j0; j < PER_B; j += 128) {
            an += (double)g_pn[rb * PER_B + j];
            ad += (double)g_pd[rb * PER_B + j];
        }
        #pragma unroll
        for (int off = 16; off > 0; off >>= 1) {
            an += __shfl_down_sync(0xFFFFFFFFu, an, off);
            ad += __shfl_down_sync(0xFFFFFFFFu, ad, off);
        }
        if (lane == 0) { wn[warp] = an; wd[warp] = ad; }
        __syncthreads();
        if (tid == 0) {
            double n0 = 0.0, dd0 = 0.0, n1 = 0.0, dd1 = 0.0;
            #pragma unroll
            for (int j = 0; j < 4; ++j) { n0 += wn[j]; dd0 += wd[j]; }
            #pragma unroll
            for (int j = 4; j < 8; ++j) { n1 += wn[j]; dd1 += wd[j]; }
            double acc = n0 / (dd0 + 1e-5) + n1 / (dd1 + 1e-5);
            out[0] = (float)(acc / (double)BB);
            g_count = 0;   // reset for next graph replay
        }
    }
}

extern "C" void kernel_launch(void* const* d_in, const int* in_sizes, int n_in,
                              void* d_out, int out_size) {
    const float* pred = (const float*)d_in[0];
    const float* tgt  = (const float*)d_in[1];
    (void)in_sizes; (void)n_in; (void)out_size;

    k_mask<<<NROWS * 32 / 256, 256>>>(tgt);         // 1536 blocks
    k_passBC<<<NBLKBC, 256>>>();                    // 1536 blocks
    k_pass3<<<NBLK3, 256>>>(pred, (float*)d_out);   // 1152 blocks
}